// round 16
// baseline (speedup 1.0000x reference)
#include <cuda_runtime.h>
#include <cuda_fp16.h>
#include <math.h>

#define HH 512
#define WW 512
#define RR 4
#define NIMG 64
#define NEL (NIMG*HH*WW)

// tile geometry: TR=32 -> no row-bound checks (512/32=16)
#define TC 32             // output cols per block
#define TR 32             // output rows per block
#define HR 40             // halo rows
#define HC 40             // halo cols
#define PP2 41            // half2 (ax,ay) plane pitch (half2s) -> conflict-free
#define PINH 42           // half plane pitch (halves)          -> conflict-free
#define PH2 33            // h plane pitch (elements)           -> conflict-free
#define PAB 41            // k_final A,b half2 pitch            -> conflict-free
#define NTHR 256
#define GY (HH / TR)      // 16

// Scratch (device global: no allocation allowed)
__device__ __half2 g_ABh[NEL];    // interleaved (A, b) in fp16

__device__ __forceinline__ unsigned h2u(__half2 v) {
    return *reinterpret_cast<unsigned*>(&v);
}
__device__ __forceinline__ __half2 u2h(unsigned v) {
    return *reinterpret_cast<__half2*>(&v);
}

// ---------------- Stage 1: fused 5-quantity box filter -> (A,b) ----------------
// Quantities: a, ax, ay, a2xy=ax*ay, a2x2=ax^2 (S-corrections dropped).
// ALL staging/h-planes fp16. FG packs (h1,h4 | h0,h3) as uint2, K holds h5=ax.
// smem 23.1 KB -> 8 blocks/SM (64 warps).
// Phase-B tail (rows 32..39): 256 single-col 9-tap runs (all threads active)
// instead of 64 threads x 15-tap runs -> phase-B wall 30 -> 24 tap-times.
__global__ __launch_bounds__(NTHR, 8) void k_stats(
    const float* __restrict__ X, const float* __restrict__ Y,
    const float* __restrict__ Wt)
{
    extern __shared__ unsigned char smem_raw[];
    __half2* sP  = (__half2*)smem_raw;               // [HR*PP2] (ax, ay)
    __half*  sAh = (__half*)(sP + HR * PP2);         // [HR*PINH] a
    uint2*   sFG = (uint2*)(sAh + HR * PINH);        // [(h1,h4),(h0,h3)]
    __half*  sK  = (__half*)(sFG + HR * PH2);        // h5=ax

    const int tid = threadIdx.x;
    const int img = blockIdx.z;
    const int bc  = blockIdx.x * TC;
    const int br  = blockIdx.y * TR;
    const size_t ibase = (size_t)img * (HH * WW);

    // ---- Phase A: vectorized halo load (zero outside = truncated box) ----
    #pragma unroll
    for (int it = 0; it < 2; ++it) {
        const int idx = tid + it * NTHR;
        if (idx < HR * (HC / 4)) {                 // 400 items
            const int rh = idx / (HC / 4);
            const int vq = idx % (HC / 4);
            const int gr = br - RR + rh;
            const int gc = bc - RR + vq * 4;       // multiple of 4, aligned
            float4 xv = make_float4(0.f,0.f,0.f,0.f);
            float4 yv = xv, av = xv;
            if (gr >= 0 && gr < HH && gc >= 0 && gc < WW) {
                const size_t o = ibase + (size_t)gr * WW + gc;
                xv = *(const float4*)(X  + o);
                yv = *(const float4*)(Y  + o);
                av = *(const float4*)(Wt + o);
            }
            const float a0 = fabsf(av.x)+1e-12f, a1 = fabsf(av.y)+1e-12f;
            const float a2 = fabsf(av.z)+1e-12f, a3 = fabsf(av.w)+1e-12f;
            const int sb2 = rh * PP2 + vq * 4;
            sP[sb2+0] = __floats2half2_rn(a0*xv.x, a0*yv.x);
            sP[sb2+1] = __floats2half2_rn(a1*xv.y, a1*yv.y);
            sP[sb2+2] = __floats2half2_rn(a2*xv.z, a2*yv.z);
            sP[sb2+3] = __floats2half2_rn(a3*xv.w, a3*yv.w);
            const int sbh = rh * PINH + vq * 4;
            sAh[sbh+0] = __float2half_rn(a0);
            sAh[sbh+1] = __float2half_rn(a1);
            sAh[sbh+2] = __float2half_rn(a2);
            sAh[sbh+3] = __float2half_rn(a3);
        }
    }
    __syncthreads();

    // ---- Phase B step 0: rows 0..31, 4-col sliding runs, 256 threads ----
    {
        const int rh = tid & 31;
        const int cg = tid >> 5;
        const int b2 = rh * PP2  + cg * 4;
        const int bH = rh * PINH + cg * 4;
        const int hb = rh * PH2  + cg * 4;

        float h0=0.f,h1=0.f,h3=0.f,h4=0.f,h5=0.f;
        #pragma unroll
        for (int d = 0; d < 9; ++d) {
            const float2 p = __half22float2(sP[b2 + d]);   // (ax, ay)
            const float  a = __half2float(sAh[bH + d]);
            h0 += a; h5 += p.x; h3 += p.y;
            h1 = fmaf(p.x, p.y, h1);                       // a2xy
            h4 = fmaf(p.x, p.x, h4);                       // a2x2
        }
        sFG[hb] = make_uint2(h2u(__floats2half2_rn(h1, h4)),
                             h2u(__floats2half2_rn(h0, h3)));
        sK[hb] = __float2half_rn(h5);

        #pragma unroll
        for (int s = 1; s < 4; ++s) {
            float2 p = __half22float2(sP[b2 + 8 + s]);
            float  a = __half2float(sAh[bH + 8 + s]);
            h0 += a; h5 += p.x; h3 += p.y;
            h1 = fmaf(p.x, p.y, h1);
            h4 = fmaf(p.x, p.x, h4);
            p = __half22float2(sP[b2 + s - 1]);
            a = __half2float(sAh[bH + s - 1]);
            h0 -= a; h5 -= p.x; h3 -= p.y;
            h1 = fmaf(-p.x, p.y, h1);
            h4 = fmaf(-p.x, p.x, h4);
            sFG[hb+s] = make_uint2(h2u(__floats2half2_rn(h1, h4)),
                                   h2u(__floats2half2_rn(h0, h3)));
            sK[hb+s] = __float2half_rn(h5);
        }
    }

    // ---- Phase B step 1: rows 32..39, single-col 9-tap runs, 256 threads ----
    {
        const int rh = 32 + (tid >> 5);       // warp -> one row
        const int c  = tid & 31;              // lane -> one col
        const int b2 = rh * PP2  + c;
        const int bH = rh * PINH + c;
        const int hb = rh * PH2  + c;

        float h0=0.f,h1=0.f,h3=0.f,h4=0.f,h5=0.f;
        #pragma unroll
        for (int d = 0; d < 9; ++d) {
            const float2 p = __half22float2(sP[b2 + d]);
            const float  a = __half2float(sAh[bH + d]);
            h0 += a; h5 += p.x; h3 += p.y;
            h1 = fmaf(p.x, p.y, h1);
            h4 = fmaf(p.x, p.x, h4);
        }
        sFG[hb] = make_uint2(h2u(__floats2half2_rn(h1, h4)),
                             h2u(__floats2half2_rn(h0, h3)));
        sK[hb] = __float2half_rn(h5);
    }
    __syncthreads();

    // ---- Phase C: vertical 9-tap, 4-row runs, all 256 threads + solve ----
    {
        const int c   = tid & 31;
        const int seg = tid >> 5;            // 0..7 -> rows seg*4 ..
        const int col = bc + c;
        const int ncl = min(col + RR, WW - 1) - max(col - RR, 0) + 1;
        const int r0 = seg * 4;

        float a0=0.f,a1=0.f,a3=0.f,a4=0.f,a5=0.f;
        #pragma unroll
        for (int d = 0; d < 9; ++d) {
            const int hb = (r0 + d) * PH2 + c;
            const uint2 fg = sFG[hb];
            const float2 f = __half22float2(u2h(fg.x));   // (h1, h4)
            const float2 g = __half22float2(u2h(fg.y));   // (h0, h3)
            a1 += f.x; a4 += f.y;
            a0 += g.x; a3 += g.y;
            a5 += __half2float(sK[hb]);
        }
        #pragma unroll
        for (int i = 0; i < 4; ++i) {
            const int gro = br + r0 + i;     // always < HH (512 = 16*32)
            {
                const int nr = min(gro + RR, HH - 1) - max(gro - RR, 0) + 1;
                const float Nf  = (float)(nr * ncl);
                const float den = fabsf(a4) + Nf * 1e-8f;
                const float Av  = __fdividef(a1, den);
                const float bv  = __fdividef(fmaf(-Av, a5, a3), a0);
                g_ABh[ibase + (size_t)gro * WW + col] = __floats2half2_rn(Av, bv);
            }
            if (i < 3) {
                const int ha = (r0 + 9 + i) * PH2 + c;
                const int hs = (r0 + i) * PH2 + c;
                const uint2 fga = sFG[ha], fgs = sFG[hs];
                const float2 fa = __half22float2(u2h(fga.x));
                const float2 fs = __half22float2(u2h(fgs.x));
                const float2 ga = __half22float2(u2h(fga.y));
                const float2 gs = __half22float2(u2h(fgs.y));
                a1 += fa.x - fs.x; a4 += fa.y - fs.y;
                a0 += ga.x - gs.x; a3 += ga.y - gs.y;
                a5 += __half2float(sK[ha]) - __half2float(sK[hs]);
            }
        }
    }
}

// ---------------- Stage 2: box filter (A,b) fp16 + final blend -----------------
// R14 config (TR=32, 256 thr) with the balanced phase-B tail.
__global__ __launch_bounds__(NTHR) void k_final(
    const float* __restrict__ X, float* __restrict__ out)
{
    __shared__ __half2 sABh[HR * PAB];      // (A, b) fp16
    __shared__ __half2 sHab[HR * PH2];      // h sums fp16

    const int tid = threadIdx.x;
    const int img = blockIdx.z;
    const int bc  = blockIdx.x * TC;
    const int br  = blockIdx.y * TR;
    const size_t ibase = (size_t)img * (HH * WW);

    // Phase A: uint4 = 4 pixels of half2 (A,b); 400 items
    #pragma unroll
    for (int it = 0; it < 2; ++it) {
        const int idx = tid + it * NTHR;
        if (idx < HR * (HC / 4)) {
            const int rh = idx / (HC / 4);
            const int vq = idx % (HC / 4);
            const int gr = br - RR + rh;
            const int gc = bc - RR + vq * 4;      // multiple of 4 -> 16B aligned
            uint4 v = make_uint4(0u, 0u, 0u, 0u);
            if (gr >= 0 && gr < HH && gc >= 0 && gc < WW) {
                const size_t o = ibase + (size_t)gr * WW + gc;
                v = *(const uint4*)(g_ABh + o);
            }
            const int sb = rh * PAB + vq * 4;
            sABh[sb+0] = u2h(v.x);
            sABh[sb+1] = u2h(v.y);
            sABh[sb+2] = u2h(v.z);
            sABh[sb+3] = u2h(v.w);
        }
    }
    __syncthreads();

    // Phase B step 0: rows 0..31, 4-col sliding runs, 256 threads
    {
        const int rh = tid & 31;
        const int cg = tid >> 5;
        const int b2 = rh * PAB + cg * 4;
        const int hb = rh * PH2 + cg * 4;
        float hA = 0.f, hB = 0.f;
        #pragma unroll
        for (int d = 0; d < 9; ++d) {
            const float2 ab = __half22float2(sABh[b2 + d]);
            hA += ab.x; hB += ab.y;
        }
        sHab[hb] = __floats2half2_rn(hA, hB);
        #pragma unroll
        for (int s = 1; s < 4; ++s) {
            const float2 aa = __half22float2(sABh[b2 + 8 + s]);
            const float2 as = __half22float2(sABh[b2 + s - 1]);
            hA += aa.x - as.x;
            hB += aa.y - as.y;
            sHab[hb + s] = __floats2half2_rn(hA, hB);
        }
    }

    // Phase B step 1: rows 32..39, single-col 9-tap runs, 256 threads
    {
        const int rh = 32 + (tid >> 5);
        const int c  = tid & 31;
        const int b2 = rh * PAB + c;
        const int hb = rh * PH2 + c;
        float hA = 0.f, hB = 0.f;
        #pragma unroll
        for (int d = 0; d < 9; ++d) {
            const float2 ab = __half22float2(sABh[b2 + d]);
            hA += ab.x; hB += ab.y;
        }
        sHab[hb] = __floats2half2_rn(hA, hB);
    }
    __syncthreads();

    // Phase C: vertical 9-tap, 4-row runs, all 256 threads + blend
    {
        const int c   = tid & 31;
        const int seg = tid >> 5;
        const int col = bc + c;
        const int ncl = min(col + RR, WW - 1) - max(col - RR, 0) + 1;
        const int r0 = seg * 4;

        float xv[4];
        #pragma unroll
        for (int i = 0; i < 4; ++i)
            xv[i] = X[ibase + (size_t)(br + r0 + i) * WW + col];

        float aA = 0.f, aB = 0.f;
        #pragma unroll
        for (int d = 0; d < 9; ++d) {
            const float2 h = __half22float2(sHab[(r0 + d) * PH2 + c]);
            aA += h.x; aB += h.y;
        }
        #pragma unroll
        for (int i = 0; i < 4; ++i) {
            const int gro = br + r0 + i;     // always < HH
            const int nr = min(gro + RR, HH - 1) - max(gro - RR, 0) + 1;
            const float rcpN = __fdividef(1.f, (float)(nr * ncl));
            out[ibase + (size_t)gro * WW + col] = (aA * xv[i] + aB) * rcpN;
            if (i < 3) {
                const float2 ha = __half22float2(sHab[(r0 + 9 + i) * PH2 + c]);
                const float2 hs = __half22float2(sHab[(r0 + i) * PH2 + c]);
                aA += ha.x - hs.x;
                aB += ha.y - hs.y;
            }
        }
    }
}

extern "C" void kernel_launch(void* const* d_in, const int* in_sizes, int n_in,
                              void* d_out, int out_size) {
    const float* x = (const float*)d_in[0];  // lr_x
    const float* y = (const float*)d_in[1];  // lr_y
    const float* a = (const float*)d_in[2];  // l_a
    float* out = (float*)d_out;

    // smem: P 6560 + a 3360 + FG 10560 + K 2640 = 23120 B -> 8 blocks/SM (64 warps)
    const int smem_stats = HR * PP2 * 4 + HR * PINH * 2
                         + HR * PH2 * 8 + HR * PH2 * 2;
    cudaFuncSetAttribute(k_stats, cudaFuncAttributeMaxDynamicSharedMemorySize, smem_stats);

    dim3 grid(WW / TC, GY, NIMG);  // 16 x 16 x 64
    k_stats<<<grid, NTHR, smem_stats>>>(x, y, a);
    k_final<<<grid, NTHR>>>(x, out);
}

// round 17
// speedup vs baseline: 1.0620x; 1.0620x over previous
#include <cuda_runtime.h>
#include <cuda_fp16.h>
#include <math.h>

#define HH 512
#define WW 512
#define RR 4
#define NIMG 64
#define NEL (NIMG*HH*WW)

// tile geometry: TR=32 -> no row-bound checks (512/32=16)
#define TC 32             // output cols per block
#define TR 32             // output rows per block
#define HR 40             // halo rows
#define HC 40             // halo cols
#define PP2 41            // half2 (ax,ay) plane pitch (half2s) -> conflict-free
#define PINH 42           // half plane pitch (halves)          -> conflict-free
#define PH2 33            // h plane pitch (elements)           -> conflict-free
#define PAB 41            // k_final A,b half2 pitch            -> conflict-free
#define NTHR 256
#define GY (HH / TR)      // 16

// Scratch (device global: no allocation allowed)
__device__ __half2 g_ABh[NEL];    // interleaved (A, b) in fp16

__device__ __forceinline__ unsigned h2u(__half2 v) {
    return *reinterpret_cast<unsigned*>(&v);
}
__device__ __forceinline__ __half2 u2h(unsigned v) {
    return *reinterpret_cast<__half2*>(&v);
}

// ---------------- Stage 1: fused 5-quantity box filter -> (A,b) ----------------
// EXACT R14 structure (best known). Quantities: a, ax, ay, a2xy, a2x2.
// ALL staging/h-planes fp16. FG packs (h1,h4 | h0,h3) as uint2, K holds h5=ax.
// smem 23.1 KB -> 8 blocks/SM (64 warps).
__global__ __launch_bounds__(NTHR, 8) void k_stats(
    const float* __restrict__ X, const float* __restrict__ Y,
    const float* __restrict__ Wt)
{
    extern __shared__ unsigned char smem_raw[];
    __half2* sP  = (__half2*)smem_raw;               // [HR*PP2] (ax, ay)
    __half*  sAh = (__half*)(sP + HR * PP2);         // [HR*PINH] a
    uint2*   sFG = (uint2*)(sAh + HR * PINH);        // [(h1,h4),(h0,h3)]
    __half*  sK  = (__half*)(sFG + HR * PH2);        // h5=ax

    const int tid = threadIdx.x;
    const int img = blockIdx.z;
    const int bc  = blockIdx.x * TC;
    const int br  = blockIdx.y * TR;
    const size_t ibase = (size_t)img * (HH * WW);

    // ---- Phase A: vectorized halo load (zero outside = truncated box) ----
    #pragma unroll
    for (int it = 0; it < 2; ++it) {
        const int idx = tid + it * NTHR;
        if (idx < HR * (HC / 4)) {                 // 400 items
            const int rh = idx / (HC / 4);
            const int vq = idx % (HC / 4);
            const int gr = br - RR + rh;
            const int gc = bc - RR + vq * 4;       // multiple of 4, aligned
            float4 xv = make_float4(0.f,0.f,0.f,0.f);
            float4 yv = xv, av = xv;
            if (gr >= 0 && gr < HH && gc >= 0 && gc < WW) {
                const size_t o = ibase + (size_t)gr * WW + gc;
                xv = *(const float4*)(X  + o);
                yv = *(const float4*)(Y  + o);
                av = *(const float4*)(Wt + o);
            }
            const float a0 = fabsf(av.x)+1e-12f, a1 = fabsf(av.y)+1e-12f;
            const float a2 = fabsf(av.z)+1e-12f, a3 = fabsf(av.w)+1e-12f;
            const int sb2 = rh * PP2 + vq * 4;
            sP[sb2+0] = __floats2half2_rn(a0*xv.x, a0*yv.x);
            sP[sb2+1] = __floats2half2_rn(a1*xv.y, a1*yv.y);
            sP[sb2+2] = __floats2half2_rn(a2*xv.z, a2*yv.z);
            sP[sb2+3] = __floats2half2_rn(a3*xv.w, a3*yv.w);
            const int sbh = rh * PINH + vq * 4;
            sAh[sbh+0] = __float2half_rn(a0);
            sAh[sbh+1] = __float2half_rn(a1);
            sAh[sbh+2] = __float2half_rn(a2);
            sAh[sbh+3] = __float2half_rn(a3);
        }
    }
    __syncthreads();

    // ---- Phase B: horizontal 9-tap, sliding over 4 cols per thread ----
    // step 0: rows 0..31 (256 threads); step 1: rows 32..39 (64 threads).
    // (R16's "balanced" tail issued MORE total instructions and regressed —
    //  this layout is instruction-minimal for the issue-bound regime.)
    #pragma unroll
    for (int step = 0; step < 2; ++step) {
        int rh, cg;
        bool act;
        if (step == 0) { rh = tid & 31;          cg = tid >> 5; act = true; }
        else           { rh = 32 + (tid & 7);    cg = tid >> 3; act = (tid < 64); }
        if (act) {
            const int b2 = rh * PP2  + cg * 4;
            const int bH = rh * PINH + cg * 4;
            const int hb = rh * PH2  + cg * 4;

            float h0=0.f,h1=0.f,h3=0.f,h4=0.f,h5=0.f;
            #pragma unroll
            for (int d = 0; d < 9; ++d) {
                const float2 p = __half22float2(sP[b2 + d]);   // (ax, ay)
                const float  a = __half2float(sAh[bH + d]);
                h0 += a; h5 += p.x; h3 += p.y;
                h1 = fmaf(p.x, p.y, h1);                       // a2xy
                h4 = fmaf(p.x, p.x, h4);                       // a2x2
            }
            sFG[hb] = make_uint2(h2u(__floats2half2_rn(h1, h4)),
                                 h2u(__floats2half2_rn(h0, h3)));
            sK[hb] = __float2half_rn(h5);

            #pragma unroll
            for (int s = 1; s < 4; ++s) {
                float2 p = __half22float2(sP[b2 + 8 + s]);
                float  a = __half2float(sAh[bH + 8 + s]);
                h0 += a; h5 += p.x; h3 += p.y;
                h1 = fmaf(p.x, p.y, h1);
                h4 = fmaf(p.x, p.x, h4);
                p = __half22float2(sP[b2 + s - 1]);
                a = __half2float(sAh[bH + s - 1]);
                h0 -= a; h5 -= p.x; h3 -= p.y;
                h1 = fmaf(-p.x, p.y, h1);
                h4 = fmaf(-p.x, p.x, h4);
                sFG[hb+s] = make_uint2(h2u(__floats2half2_rn(h1, h4)),
                                       h2u(__floats2half2_rn(h0, h3)));
                sK[hb+s] = __float2half_rn(h5);
            }
        }
    }
    __syncthreads();

    // ---- Phase C: vertical 9-tap, 4-row runs, all 256 threads + solve ----
    {
        const int c   = tid & 31;
        const int seg = tid >> 5;            // 0..7 -> rows seg*4 ..
        const int col = bc + c;
        const int ncl = min(col + RR, WW - 1) - max(col - RR, 0) + 1;
        const int r0 = seg * 4;

        float a0=0.f,a1=0.f,a3=0.f,a4=0.f,a5=0.f;
        #pragma unroll
        for (int d = 0; d < 9; ++d) {
            const int hb = (r0 + d) * PH2 + c;
            const uint2 fg = sFG[hb];
            const float2 f = __half22float2(u2h(fg.x));   // (h1, h4)
            const float2 g = __half22float2(u2h(fg.y));   // (h0, h3)
            a1 += f.x; a4 += f.y;
            a0 += g.x; a3 += g.y;
            a5 += __half2float(sK[hb]);
        }
        #pragma unroll
        for (int i = 0; i < 4; ++i) {
            const int gro = br + r0 + i;     // always < HH (512 = 16*32)
            {
                const int nr = min(gro + RR, HH - 1) - max(gro - RR, 0) + 1;
                const float Nf  = (float)(nr * ncl);
                const float den = fabsf(a4) + Nf * 1e-8f;
                const float Av  = __fdividef(a1, den);
                const float bv  = __fdividef(fmaf(-Av, a5, a3), a0);
                g_ABh[ibase + (size_t)gro * WW + col] = __floats2half2_rn(Av, bv);
            }
            if (i < 3) {
                const int ha = (r0 + 9 + i) * PH2 + c;
                const int hs = (r0 + i) * PH2 + c;
                const uint2 fga = sFG[ha], fgs = sFG[hs];
                const float2 fa = __half22float2(u2h(fga.x));
                const float2 fs = __half22float2(u2h(fgs.x));
                const float2 ga = __half22float2(u2h(fga.y));
                const float2 gs = __half22float2(u2h(fgs.y));
                a1 += fa.x - fs.x; a4 += fa.y - fs.y;
                a0 += ga.x - gs.x; a3 += ga.y - gs.y;
                a5 += __half2float(sK[ha]) - __half2float(sK[hs]);
            }
        }
    }
}

// ---------------- Stage 2: box filter (A,b) fp16 + final blend -----------------
// R14 config; phase B now accumulates in packed fp16 (HADD2/HSUB2) — no
// converts, ~45% fewer phase-B instructions; result was fp16-stored anyway.
__global__ __launch_bounds__(NTHR) void k_final(
    const float* __restrict__ X, float* __restrict__ out)
{
    __shared__ __half2 sABh[HR * PAB];      // (A, b) fp16
    __shared__ __half2 sHab[HR * PH2];      // h sums fp16

    const int tid = threadIdx.x;
    const int img = blockIdx.z;
    const int bc  = blockIdx.x * TC;
    const int br  = blockIdx.y * TR;
    const size_t ibase = (size_t)img * (HH * WW);

    // Phase A: uint4 = 4 pixels of half2 (A,b); 400 items
    #pragma unroll
    for (int it = 0; it < 2; ++it) {
        const int idx = tid + it * NTHR;
        if (idx < HR * (HC / 4)) {
            const int rh = idx / (HC / 4);
            const int vq = idx % (HC / 4);
            const int gr = br - RR + rh;
            const int gc = bc - RR + vq * 4;      // multiple of 4 -> 16B aligned
            uint4 v = make_uint4(0u, 0u, 0u, 0u);
            if (gr >= 0 && gr < HH && gc >= 0 && gc < WW) {
                const size_t o = ibase + (size_t)gr * WW + gc;
                v = *(const uint4*)(g_ABh + o);
            }
            const int sb = rh * PAB + vq * 4;
            sABh[sb+0] = u2h(v.x);
            sABh[sb+1] = u2h(v.y);
            sABh[sb+2] = u2h(v.z);
            sABh[sb+3] = u2h(v.w);
        }
    }
    __syncthreads();

    // Phase B: horizontal 9-tap, 4-col runs, packed HADD2 accumulation
    #pragma unroll
    for (int step = 0; step < 2; ++step) {
        int rh, cg;
        bool act;
        if (step == 0) { rh = tid & 31;          cg = tid >> 5; act = true; }
        else           { rh = 32 + (tid & 7);    cg = tid >> 3; act = (tid < 64); }
        if (act) {
            const int b2 = rh * PAB + cg * 4;
            const int hb = rh * PH2 + cg * 4;
            __half2 acc = sABh[b2];
            #pragma unroll
            for (int d = 1; d < 9; ++d) acc = __hadd2(acc, sABh[b2 + d]);
            sHab[hb] = acc;
            #pragma unroll
            for (int s = 1; s < 4; ++s) {
                acc = __hadd2(acc, sABh[b2 + 8 + s]);
                acc = __hsub2(acc, sABh[b2 + s - 1]);
                sHab[hb + s] = acc;
            }
        }
    }
    __syncthreads();

    // Phase C: vertical 9-tap, 4-row runs, all 256 threads + blend (fp32 acc)
    {
        const int c   = tid & 31;
        const int seg = tid >> 5;
        const int col = bc + c;
        const int ncl = min(col + RR, WW - 1) - max(col - RR, 0) + 1;
        const int r0 = seg * 4;

        float xv[4];
        #pragma unroll
        for (int i = 0; i < 4; ++i)
            xv[i] = X[ibase + (size_t)(br + r0 + i) * WW + col];

        float aA = 0.f, aB = 0.f;
        #pragma unroll
        for (int d = 0; d < 9; ++d) {
            const float2 h = __half22float2(sHab[(r0 + d) * PH2 + c]);
            aA += h.x; aB += h.y;
        }
        #pragma unroll
        for (int i = 0; i < 4; ++i) {
            const int gro = br + r0 + i;     // always < HH
            const int nr = min(gro + RR, HH - 1) - max(gro - RR, 0) + 1;
            const float rcpN = __fdividef(1.f, (float)(nr * ncl));
            out[ibase + (size_t)gro * WW + col] = (aA * xv[i] + aB) * rcpN;
            if (i < 3) {
                const float2 ha = __half22float2(sHab[(r0 + 9 + i) * PH2 + c]);
                const float2 hs = __half22float2(sHab[(r0 + i) * PH2 + c]);
                aA += ha.x - hs.x;
                aB += ha.y - hs.y;
            }
        }
    }
}

extern "C" void kernel_launch(void* const* d_in, const int* in_sizes, int n_in,
                              void* d_out, int out_size) {
    const float* x = (const float*)d_in[0];  // lr_x
    const float* y = (const float*)d_in[1];  // lr_y
    const float* a = (const float*)d_in[2];  // l_a
    float* out = (float*)d_out;

    // smem: P 6560 + a 3360 + FG 10560 + K 2640 = 23120 B -> 8 blocks/SM (64 warps)
    const int smem_stats = HR * PP2 * 4 + HR * PINH * 2
                         + HR * PH2 * 8 + HR * PH2 * 2;
    cudaFuncSetAttribute(k_stats, cudaFuncAttributeMaxDynamicSharedMemorySize, smem_stats);

    dim3 grid(WW / TC, GY, NIMG);  // 16 x 16 x 64
    k_stats<<<grid, NTHR, smem_stats>>>(x, y, a);
    k_final<<<grid, NTHR>>>(x, out);
}